// round 1
// baseline (speedup 1.0000x reference)
#include <cuda_runtime.h>
#include <math.h>

#define N_NODES 50000
#define N_EDGES 800000
#define NF 64

// Scratch (static __device__ arrays per allocation rules)
__device__ __align__(16) float g_h[N_NODES * NF];          // 12.8 MB
__device__ __align__(16) float g_phi[N_NODES * 3 * NF];    // 38.4 MB

// ---------- f32x2 helpers (Blackwell packed fp32) ----------
__device__ __forceinline__ unsigned long long pack2(float lo, float hi) {
    unsigned long long r;
    asm("mov.b64 %0, {%1, %2};" : "=l"(r) : "f"(lo), "f"(hi));
    return r;
}
__device__ __forceinline__ float2 unpack2(unsigned long long x) {
    float2 f;
    asm("mov.b64 {%0, %1}, %2;" : "=f"(f.x), "=f"(f.y) : "l"(x));
    return f;
}
#define FMA2(d, a, b, c) \
    asm("fma.rn.f32x2 %0, %1, %2, %3;" : "=l"(d) : "l"(a), "l"(b), "l"(c))

// Vectored no-return global reduction (sm_90+)
__device__ __forceinline__ void red_add_v4(float* p, float a, float b, float c, float d) {
    asm volatile("red.global.add.v4.f32 [%0], {%1, %2, %3, %4};"
                 :: "l"(p), "f"(a), "f"(b), "f"(c), "f"(d) : "memory");
}

// ---------- Kernel 0: out = [s | v] (atomics accumulate on top) ----------
__global__ void k_init(const float4* __restrict__ s4, const float4* __restrict__ v4,
                       float4* __restrict__ out4) {
    const int NS4 = N_NODES * NF / 4;      // 800000
    const int NV4 = N_NODES * 3 * NF / 4;  // 2400000
    int i = blockIdx.x * 256 + threadIdx.x;
    if (i < NS4) {
        out4[i] = s4[i];
    } else {
        int k = i - NS4;
        if (k < NV4) out4[NS4 + k] = v4[k];
    }
}

// ---------- Kernel 1: h = silu(s @ W1 + b1) ----------
// 16 nodes / block, 256 threads: thread = (channel c, node-quartet q)
__global__ void k_h(const float* __restrict__ s, const float* __restrict__ W1,
                    const float* __restrict__ b1) {
    __shared__ float sW1[NF * NF];     // 16 KB
    __shared__ float sS[16 * NF];      // 4 KB
    int tid = threadIdx.x;
    int node0 = blockIdx.x * 16;
    for (int i = tid; i < NF * NF; i += 256) sW1[i] = W1[i];
    for (int i = tid; i < 16 * NF; i += 256) sS[i] = s[node0 * NF + i];
    __syncthreads();

    int c = tid & 63;
    int q = tid >> 6;  // node quartet
    float b = b1[c];
    float a0 = b, a1 = b, a2 = b, a3 = b;
    const float* sr = &sS[q * 4 * NF];
#pragma unroll 8
    for (int k = 0; k < NF; k++) {
        float w = sW1[k * NF + c];
        a0 += sr[k] * w;
        a1 += sr[NF + k] * w;
        a2 += sr[2 * NF + k] * w;
        a3 += sr[3 * NF + k] * w;
    }
    int o = (node0 + q * 4) * NF + c;
    g_h[o]          = a0 / (1.f + expf(-a0));
    g_h[o + NF]     = a1 / (1.f + expf(-a1));
    g_h[o + 2 * NF] = a2 / (1.f + expf(-a2));
    g_h[o + 3 * NF] = a3 / (1.f + expf(-a3));
}

// ---------- Kernel 2: phi = h @ W2 + b2  (K=64, 192 outputs) ----------
// 8 nodes / block, 192 threads (one output channel each), W2 tiled 16 rows at a time
__global__ void k_phi(const float* __restrict__ W2, const float* __restrict__ b2) {
    __shared__ float sW2[16 * 192];    // 12 KB
    __shared__ float sH[8 * NF];       // 2 KB
    int tid = threadIdx.x;
    int node0 = blockIdx.x * 8;
    for (int i = tid; i < 8 * NF; i += 192) sH[i] = g_h[node0 * NF + i];

    float acc[8];
    float b = b2[tid];
#pragma unroll
    for (int n = 0; n < 8; n++) acc[n] = b;

    for (int kt = 0; kt < NF; kt += 16) {
        __syncthreads();
        for (int i = tid; i < 16 * 192; i += 192) sW2[i] = W2[kt * 192 + i];
        __syncthreads();
#pragma unroll
        for (int kk = 0; kk < 16; kk++) {
            float w = sW2[kk * 192 + tid];
#pragma unroll
            for (int n = 0; n < 8; n++) acc[n] += sH[n * NF + kt + kk] * w;
        }
    }
#pragma unroll
    for (int n = 0; n < 8; n++) g_phi[(node0 + n) * 192 + tid] = acc[n];
}

// ---------- Kernel 3: fused edge kernel ----------
// 64 edges / block, 256 threads. Thread = (channel-group g in [0,16), edge-quartet eq in [0,16)).
// Each thread: 12 output channels (4 per section) x 4 edges, f32x2 FMAs.
__global__ void __launch_bounds__(256) k_edge(
    const float* __restrict__ v, const float* __restrict__ radial,
    const float* __restrict__ f_cut, const float* __restrict__ uvec,
    const int* __restrict__ eidx, const float* __restrict__ Wr,
    const float* __restrict__ br, float* __restrict__ out) {
    __shared__ __align__(16) float sWr[32 * 192];  // 24 KB
    __shared__ float sBr[192];
    __shared__ float sRad[64 * 33];                // padded (bank-conflict avoid)
    __shared__ int sI[64], sJ[64];
    __shared__ float sFc[64];
    __shared__ float sU[64 * 3];

    int tid = threadIdx.x;
    int e0 = blockIdx.x * 64;

    for (int i = tid; i < 32 * 192; i += 256) sWr[i] = Wr[i];
    if (tid < 192) sBr[tid] = br[tid];
    for (int i = tid; i < 64 * 32; i += 256) {
        int e = i >> 5, r = i & 31;
        sRad[e * 33 + r] = radial[(size_t)e0 * 32 + i];
    }
    if (tid < 64) {
        sI[tid] = eidx[e0 + tid];
        sJ[tid] = eidx[N_EDGES + e0 + tid];
        sFc[tid] = f_cut[e0 + tid];
    }
    if (tid < 192) sU[tid] = uvec[(size_t)e0 * 3 + tid];
    __syncthreads();

    int g = tid & 15;   // channel group: channels 4g..4g+3 in each of 3 sections
    int eq = tid >> 4;  // edge quartet

    unsigned long long acc[4][6];
#pragma unroll
    for (int e = 0; e < 4; e++)
#pragma unroll
        for (int p = 0; p < 6; p++) acc[e][p] = 0ull;

    const unsigned long long* sWr64 = (const unsigned long long*)sWr;
#pragma unroll 4
    for (int r = 0; r < 32; r++) {
        int wb = r * 96 + 2 * g;
        unsigned long long w0 = sWr64[wb],      w1 = sWr64[wb + 1];
        unsigned long long w2 = sWr64[wb + 32], w3 = sWr64[wb + 33];
        unsigned long long w4 = sWr64[wb + 64], w5 = sWr64[wb + 65];
#pragma unroll
        for (int e = 0; e < 4; e++) {
            float rad = sRad[(eq * 4 + e) * 33 + r];
            unsigned long long rr = pack2(rad, rad);
            FMA2(acc[e][0], rr, w0, acc[e][0]);
            FMA2(acc[e][1], rr, w1, acc[e][1]);
            FMA2(acc[e][2], rr, w2, acc[e][2]);
            FMA2(acc[e][3], rr, w3, acc[e][3]);
            FMA2(acc[e][4], rr, w4, acc[e][4]);
            FMA2(acc[e][5], rr, w5, acc[e][5]);
        }
    }

    float bs0 = sBr[4 * g], bs1 = sBr[4 * g + 1], bs2 = sBr[4 * g + 2], bs3 = sBr[4 * g + 3];
    float bv0 = sBr[64 + 4 * g], bv1 = sBr[64 + 4 * g + 1],
          bv2 = sBr[64 + 4 * g + 2], bv3 = sBr[64 + 4 * g + 3];
    float bx0 = sBr[128 + 4 * g], bx1 = sBr[128 + 4 * g + 1],
          bx2 = sBr[128 + 4 * g + 2], bx3 = sBr[128 + 4 * g + 3];

#pragma unroll
    for (int e = 0; e < 4; e++) {
        int el = eq * 4 + e;
        int i = sI[el], j = sJ[el];
        float fc = sFc[el];

        float2 a0 = unpack2(acc[e][0]), a1 = unpack2(acc[e][1]);
        float2 a2 = unpack2(acc[e][2]), a3 = unpack2(acc[e][3]);
        float2 a4 = unpack2(acc[e][4]), a5 = unpack2(acc[e][5]);

        float Ws0 = (a0.x + bs0) * fc, Ws1 = (a0.y + bs1) * fc;
        float Ws2 = (a1.x + bs2) * fc, Ws3 = (a1.y + bs3) * fc;
        float Wv0 = (a2.x + bv0) * fc, Wv1 = (a2.y + bv1) * fc;
        float Wv2 = (a3.x + bv2) * fc, Wv3 = (a3.y + bv3) * fc;
        float Wx0 = (a4.x + bx0) * fc, Wx1 = (a4.y + bx1) * fc;
        float Wx2 = (a5.x + bx2) * fc, Wx3 = (a5.y + bx3) * fc;

        const float4 ps = *(const float4*)&g_phi[j * 192 + 4 * g];
        const float4 pv = *(const float4*)&g_phi[j * 192 + 64 + 4 * g];
        const float4 px = *(const float4*)&g_phi[j * 192 + 128 + 4 * g];

        float xs0 = ps.x * Ws0, xs1 = ps.y * Ws1, xs2 = ps.z * Ws2, xs3 = ps.w * Ws3;
        float xvv0 = pv.x * Wv0, xvv1 = pv.y * Wv1, xvv2 = pv.z * Wv2, xvv3 = pv.w * Wv3;
        float xvs0 = px.x * Wx0, xvs1 = px.y * Wx1, xvs2 = px.z * Wx2, xvs3 = px.w * Wx3;

        red_add_v4(out + i * NF + 4 * g, xs0, xs1, xs2, xs3);

        float u0 = sU[el * 3 + 0], u1 = sU[el * 3 + 1], u2 = sU[el * 3 + 2];
#pragma unroll
        for (int d = 0; d < 3; d++) {
            float ud = (d == 0) ? u0 : ((d == 1) ? u1 : u2);
            const float4 vd = *(const float4*)&v[(size_t)j * 192 + d * 64 + 4 * g];
            float dv0 = vd.x * xvv0 + xvs0 * ud;
            float dv1 = vd.y * xvv1 + xvs1 * ud;
            float dv2 = vd.z * xvv2 + xvs2 * ud;
            float dv3 = vd.w * xvv3 + xvs3 * ud;
            red_add_v4(out + N_NODES * NF + i * 192 + d * 64 + 4 * g, dv0, dv1, dv2, dv3);
        }
    }
}

extern "C" void kernel_launch(void* const* d_in, const int* in_sizes, int n_in,
                              void* d_out, int out_size) {
    const float* s      = (const float*)d_in[0];
    const float* v      = (const float*)d_in[1];
    const float* radial = (const float*)d_in[2];
    const float* f_cut  = (const float*)d_in[3];
    const float* uvec   = (const float*)d_in[4];
    const int*   eidx   = (const int*)d_in[5];
    const float* W1     = (const float*)d_in[6];
    const float* b1     = (const float*)d_in[7];
    const float* W2     = (const float*)d_in[8];
    const float* b2     = (const float*)d_in[9];
    const float* Wr     = (const float*)d_in[10];
    const float* br     = (const float*)d_in[11];
    float* out = (float*)d_out;

    // out = [s | v]
    k_init<<<(N_NODES * NF + N_NODES * 3 * NF) / 4 / 256, 256>>>(
        (const float4*)s, (const float4*)v, (float4*)out);
    // phi
    k_h<<<N_NODES / 16, 256>>>(s, W1, b1);
    k_phi<<<N_NODES / 8, 192>>>(W2, b2);
    // fused edge message + scatter
    k_edge<<<N_EDGES / 64, 256>>>(v, radial, f_cut, uvec, eidx, Wr, br, out);
}

// round 6
// speedup vs baseline: 1.1926x; 1.1926x over previous
#include <cuda_runtime.h>
#include <math.h>

#define N_NODES 50000
#define N_EDGES 800000
#define NF 64

// Scratch (static __device__ arrays per allocation rules)
__device__ __align__(16) float g_h[N_NODES * NF];          // 12.8 MB
__device__ __align__(16) float g_phi[N_NODES * 3 * NF];    // 38.4 MB

// ---------- f32x2 helpers (Blackwell packed fp32) ----------
__device__ __forceinline__ unsigned long long pack2(float lo, float hi) {
    unsigned long long r;
    asm("mov.b64 %0, {%1, %2};" : "=l"(r) : "f"(lo), "f"(hi));
    return r;
}
__device__ __forceinline__ float2 unpack2(unsigned long long x) {
    float2 f;
    asm("mov.b64 {%0, %1}, %2;" : "=f"(f.x), "=f"(f.y) : "l"(x));
    return f;
}
#define FMA2(d, a, b, c) \
    asm("fma.rn.f32x2 %0, %1, %2, %3;" : "=l"(d) : "l"(a), "l"(b), "l"(c))

// Vectored no-return global reduction (sm_90+)
__device__ __forceinline__ void red_add_v4(float* p, float a, float b, float c, float d) {
    asm volatile("red.global.add.v4.f32 [%0], {%1, %2, %3, %4};"
                 :: "l"(p), "f"(a), "f"(b), "f"(c), "f"(d) : "memory");
}

// ---------- Kernel 0: out = [s | v] (atomics accumulate on top) ----------
__global__ void k_init(const float4* __restrict__ s4, const float4* __restrict__ v4,
                       float4* __restrict__ out4) {
    const int NS4 = N_NODES * NF / 4;      // 800000
    const int NV4 = N_NODES * 3 * NF / 4;  // 2400000
    int i = blockIdx.x * 256 + threadIdx.x;
    if (i < NS4) {
        out4[i] = s4[i];
    } else {
        int k = i - NS4;
        if (k < NV4) out4[NS4 + k] = v4[k];
    }
}

// ---------- Kernel 1: h = silu(s @ W1 + b1) ----------
__global__ void k_h(const float* __restrict__ s, const float* __restrict__ W1,
                    const float* __restrict__ b1) {
    __shared__ float sW1[NF * NF];     // 16 KB
    __shared__ float sS[16 * NF];      // 4 KB
    int tid = threadIdx.x;
    int node0 = blockIdx.x * 16;
    for (int i = tid; i < NF * NF; i += 256) sW1[i] = W1[i];
    for (int i = tid; i < 16 * NF; i += 256) sS[i] = s[node0 * NF + i];
    __syncthreads();

    int c = tid & 63;
    int q = tid >> 6;
    float b = b1[c];
    float a0 = b, a1 = b, a2 = b, a3 = b;
    const float* sr = &sS[q * 4 * NF];
#pragma unroll 8
    for (int k = 0; k < NF; k++) {
        float w = sW1[k * NF + c];
        a0 += sr[k] * w;
        a1 += sr[NF + k] * w;
        a2 += sr[2 * NF + k] * w;
        a3 += sr[3 * NF + k] * w;
    }
    int o = (node0 + q * 4) * NF + c;
    g_h[o]          = a0 / (1.f + expf(-a0));
    g_h[o + NF]     = a1 / (1.f + expf(-a1));
    g_h[o + 2 * NF] = a2 / (1.f + expf(-a2));
    g_h[o + 3 * NF] = a3 / (1.f + expf(-a3));
}

// ---------- Kernel 2: phi = h @ W2 + b2  (16 nodes/block) ----------
__global__ void k_phi(const float* __restrict__ W2, const float* __restrict__ b2) {
    __shared__ float sW2[16 * 192];    // 12 KB
    __shared__ float sH[16 * NF];      // 4 KB
    int tid = threadIdx.x;
    int node0 = blockIdx.x * 16;
    for (int i = tid; i < 16 * NF; i += 192) sH[i] = g_h[node0 * NF + i];

    float acc[16];
    float b = b2[tid];
#pragma unroll
    for (int n = 0; n < 16; n++) acc[n] = b;

    for (int kt = 0; kt < NF; kt += 16) {
        __syncthreads();
        for (int i = tid; i < 16 * 192; i += 192) sW2[i] = W2[kt * 192 + i];
        __syncthreads();
#pragma unroll
        for (int kk = 0; kk < 16; kk++) {
            float w = sW2[kk * 192 + tid];
#pragma unroll
            for (int n = 0; n < 16; n++) acc[n] += sH[n * NF + kt + kk] * w;
        }
    }
#pragma unroll
    for (int n = 0; n < 16; n++) g_phi[(node0 + n) * 192 + tid] = acc[n];
}

// ---------- Kernel 3: fused edge kernel ----------
// 64 edges / block, 256 threads. Thread = (channel-group g in [0,16), edge-quartet eq).
// __launch_bounds__(256,3): cap regs at 84 so 3 CTAs/SM fit (was 106 regs -> 2 CTAs).
__global__ void __launch_bounds__(256, 3) k_edge(
    const float* __restrict__ v, const float* __restrict__ radial,
    const float* __restrict__ f_cut, const float* __restrict__ uvec,
    const int* __restrict__ eidx, const float* __restrict__ Wr,
    const float* __restrict__ br, float* __restrict__ out) {
    __shared__ __align__(16) float sWr[32 * 192];  // 24 KB
    __shared__ __align__(16) float sBr[192];
    __shared__ float sRad[64 * 33];                // padded
    __shared__ int sI[64], sJ[64];
    __shared__ float sFc[64];
    __shared__ float sU[64 * 3];

    int tid = threadIdx.x;
    int e0 = blockIdx.x * 64;

    for (int i = tid; i < 32 * 192; i += 256) sWr[i] = Wr[i];
    if (tid < 192) sBr[tid] = br[tid];
    for (int i = tid; i < 64 * 32; i += 256) {
        int e = i >> 5, r = i & 31;
        sRad[e * 33 + r] = radial[(size_t)e0 * 32 + i];
    }
    if (tid < 64) {
        sI[tid] = eidx[e0 + tid];
        sJ[tid] = eidx[N_EDGES + e0 + tid];
        sFc[tid] = f_cut[e0 + tid];
    }
    if (tid < 192) sU[tid] = uvec[(size_t)e0 * 3 + tid];
    __syncthreads();

    int g = tid & 15;   // 4 channels per section (12 channels total)
    int eq = tid >> 4;  // edge quartet

    // Init accumulators with the bias (saves 12 live bias regs + epilogue adds)
    const unsigned long long* sBr64 = (const unsigned long long*)sBr;
    unsigned long long b0 = sBr64[2 * g],      b1 = sBr64[2 * g + 1];
    unsigned long long b2_ = sBr64[32 + 2 * g], b3 = sBr64[33 + 2 * g];
    unsigned long long b4 = sBr64[64 + 2 * g], b5 = sBr64[65 + 2 * g];

    unsigned long long acc[4][6];
#pragma unroll
    for (int e = 0; e < 4; e++) {
        acc[e][0] = b0; acc[e][1] = b1; acc[e][2] = b2_;
        acc[e][3] = b3; acc[e][4] = b4; acc[e][5] = b5;
    }

    const unsigned long long* sWr64 = (const unsigned long long*)sWr;
#pragma unroll 4
    for (int r = 0; r < 32; r++) {
        int wb = r * 96 + 2 * g;
        unsigned long long w0 = sWr64[wb],      w1 = sWr64[wb + 1];
        unsigned long long w2 = sWr64[wb + 32], w3 = sWr64[wb + 33];
        unsigned long long w4 = sWr64[wb + 64], w5 = sWr64[wb + 65];
#pragma unroll
        for (int e = 0; e < 4; e++) {
            float rad = sRad[(eq * 4 + e) * 33 + r];
            unsigned long long rr = pack2(rad, rad);
            FMA2(acc[e][0], rr, w0, acc[e][0]);
            FMA2(acc[e][1], rr, w1, acc[e][1]);
            FMA2(acc[e][2], rr, w2, acc[e][2]);
            FMA2(acc[e][3], rr, w3, acc[e][3]);
            FMA2(acc[e][4], rr, w4, acc[e][4]);
            FMA2(acc[e][5], rr, w5, acc[e][5]);
        }
    }

    // Narrow-liveness epilogue: per edge, issue all 6 gathers up front,
    // then math + reductions; acc regs for edge e die inside iteration e.
#pragma unroll
    for (int e = 0; e < 4; e++) {
        int el = eq * 4 + e;
        int i = sI[el], j = sJ[el];
        float fc = sFc[el];

        const float4* pj = (const float4*)&g_phi[j * 192 + 4 * g];
        const float4* vj = (const float4*)&v[(size_t)j * 192 + 4 * g];
        float4 ps  = pj[0];
        float4 pv  = pj[16];
        float4 px  = pj[32];
        float4 vd0 = vj[0];
        float4 vd1 = vj[16];
        float4 vd2 = vj[32];

        float2 a0 = unpack2(acc[e][0]), a1 = unpack2(acc[e][1]);
        float xs0 = ps.x * (a0.x * fc), xs1 = ps.y * (a0.y * fc);
        float xs2 = ps.z * (a1.x * fc), xs3 = ps.w * (a1.y * fc);
        red_add_v4(out + i * NF + 4 * g, xs0, xs1, xs2, xs3);

        float2 a2 = unpack2(acc[e][2]), a3 = unpack2(acc[e][3]);
        float xvv0 = pv.x * (a2.x * fc), xvv1 = pv.y * (a2.y * fc);
        float xvv2 = pv.z * (a3.x * fc), xvv3 = pv.w * (a3.y * fc);

        float2 a4 = unpack2(acc[e][4]), a5 = unpack2(acc[e][5]);
        float xvs0 = px.x * (a4.x * fc), xvs1 = px.y * (a4.y * fc);
        float xvs2 = px.z * (a5.x * fc), xvs3 = px.w * (a5.y * fc);

        float u0 = sU[el * 3 + 0], u1 = sU[el * 3 + 1], u2 = sU[el * 3 + 2];
        float* ov = out + N_NODES * NF + i * 192 + 4 * g;

        red_add_v4(ov,
                   vd0.x * xvv0 + xvs0 * u0, vd0.y * xvv1 + xvs1 * u0,
                   vd0.z * xvv2 + xvs2 * u0, vd0.w * xvv3 + xvs3 * u0);
        red_add_v4(ov + 64,
                   vd1.x * xvv0 + xvs0 * u1, vd1.y * xvv1 + xvs1 * u1,
                   vd1.z * xvv2 + xvs2 * u1, vd1.w * xvv3 + xvs3 * u1);
        red_add_v4(ov + 128,
                   vd2.x * xvv0 + xvs0 * u2, vd2.y * xvv1 + xvs1 * u2,
                   vd2.z * xvv2 + xvs2 * u2, vd2.w * xvv3 + xvs3 * u2);
    }
}

extern "C" void kernel_launch(void* const* d_in, const int* in_sizes, int n_in,
                              void* d_out, int out_size) {
    const float* s      = (const float*)d_in[0];
    const float* v      = (const float*)d_in[1];
    const float* radial = (const float*)d_in[2];
    const float* f_cut  = (const float*)d_in[3];
    const float* uvec   = (const float*)d_in[4];
    const int*   eidx   = (const int*)d_in[5];
    const float* W1     = (const float*)d_in[6];
    const float* b1     = (const float*)d_in[7];
    const float* W2     = (const float*)d_in[8];
    const float* b2     = (const float*)d_in[9];
    const float* Wr     = (const float*)d_in[10];
    const float* br     = (const float*)d_in[11];
    float* out = (float*)d_out;

    k_init<<<(N_NODES * NF + N_NODES * 3 * NF) / 4 / 256, 256>>>(
        (const float4*)s, (const float4*)v, (float4*)out);
    k_h<<<N_NODES / 16, 256>>>(s, W1, b1);
    k_phi<<<N_NODES / 16, 192>>>(W2, b2);
    k_edge<<<N_EDGES / 64, 256>>>(v, radial, f_cut, uvec, eidx, Wr, br, out);
}